// round 15
// baseline (speedup 1.0000x reference)
#include <cuda_runtime.h>
#include <cuda_fp16.h>
#include <math.h>
#include <stdint.h>

#define T_SEQ 4096
#define C_DIM 2048
#define NHEAD 16
#define HS 128
#define NQG 4
#define QKV_DIM 3072
#define SCALE_LOG2 0.1275071050830161f       // (1/sqrt(128)) * log2(e)

// ---------------- scratch ----------------
__device__ __half g_qkvh[T_SEQ * QKV_DIM];    // qkv as fp16 (GEMM1 output)

__device__ __half g_xh[T_SEQ * C_DIM];        // x as fp16
__device__ __half g_wa[QKV_DIM * C_DIM];
__device__ __half g_wp[C_DIM * C_DIM];

__device__ __half g_qh[T_SEQ * NHEAD * HS];   // [t][h*128+d], scaled by SCALE_LOG2
__device__ __half g_kh[NQG * T_SEQ * HS];     // [g][t][d]
__device__ __half g_yh[T_SEQ * C_DIM];        // attention out, fp16

// ---------------- PTX helpers ----------------
__device__ __forceinline__ uint32_t smem_u32(const void* p) {
    uint32_t a;
    asm("{ .reg .u64 t; cvta.to.shared.u64 t, %1; cvt.u32.u64 %0, t; }"
        : "=r"(a) : "l"(p));
    return a;
}
__device__ __forceinline__ void cp_async16(uint32_t s, const void* g) {
    asm volatile("cp.async.cg.shared.global [%0], [%1], 16;" :: "r"(s), "l"(g));
}
#define CP_COMMIT() asm volatile("cp.async.commit_group;" ::: "memory")
#define CP_WAIT(n)  asm volatile("cp.async.wait_group %0;" :: "n"(n) : "memory")

__device__ __forceinline__ void ldsm4(uint32_t* f, uint32_t a) {
    asm volatile("ldmatrix.sync.aligned.m8n8.x4.shared.b16 {%0,%1,%2,%3}, [%4];"
                 : "=r"(f[0]), "=r"(f[1]), "=r"(f[2]), "=r"(f[3]) : "r"(a));
}
__device__ __forceinline__ void ldsm4t(uint32_t* f, uint32_t a) {
    asm volatile("ldmatrix.sync.aligned.m8n8.x4.trans.shared.b16 {%0,%1,%2,%3}, [%4];"
                 : "=r"(f[0]), "=r"(f[1]), "=r"(f[2]), "=r"(f[3]) : "r"(a));
}
__device__ __forceinline__ void mma16816(float* d, const uint32_t* a,
                                         uint32_t b0, uint32_t b1) {
    asm volatile(
        "mma.sync.aligned.m16n8k16.row.col.f32.f16.f16.f32 "
        "{%0,%1,%2,%3}, {%4,%5,%6,%7}, {%8,%9}, {%0,%1,%2,%3};"
        : "+f"(d[0]), "+f"(d[1]), "+f"(d[2]), "+f"(d[3])
        : "r"(a[0]), "r"(a[1]), "r"(a[2]), "r"(a[3]), "r"(b0), "r"(b1));
}
__device__ __forceinline__ uint32_t pack2h(float lo, float hi) {
    uint32_t r;
    asm("cvt.rn.f16x2.f32 %0, %1, %2;" : "=r"(r) : "f"(hi), "f"(lo));
    return r;
}
__device__ __forceinline__ uint32_t ex2h2(uint32_t x) {
    uint32_t r;
    asm("ex2.approx.f16x2 %0, %1;" : "=r"(r) : "r"(x));
    return r;
}

// 64B-row XOR swizzle (rows of 32 halves, 4x16B chunks) — attention tiles
__device__ __forceinline__ int sw_off(int r, int c) {
    return r * 64 + ((c ^ ((r >> 1) & 3)) << 4);
}
// 128B-row XOR swizzle (rows of 64 halves, 8x16B chunks) — GEMM tiles
__device__ __forceinline__ int sw128(int r, int c) {
    return r * 128 + (((c ^ r) & 7) << 4);
}

// ---------------- fp32 -> fp16 convert, grid-stride x4 ----------------
__global__ __launch_bounds__(256) void conv_fp16(const float4* __restrict__ s,
                                                 uint32_t* __restrict__ h, int n4) {
    int i0 = blockIdx.x * 256 + threadIdx.x;
    int stride = gridDim.x * 256;
#pragma unroll
    for (int k = 0; k < 4; k++) {
        int idx = i0 + k * stride;
        if (idx < n4) {
            float4 v = s[idx];
            h[2 * idx]     = pack2h(v.x, v.y);
            h[2 * idx + 1] = pack2h(v.z, v.w);
        }
    }
}

// ---------------- mma.sync fp16 GEMM: C = A * B^T ----------------
// CTA 256x128, 8 warps (4M x 2N), warp tile 64x64, 1 CTA/SM.
// 8 ldsm per k16 serve 32 mma (crossbar:tensor balanced 1:1). 3-stage, 1 sync/chunk.
#define BKG 64
#define TILE_A (256 * 128)      // 32KB  (256 rows x 64 halves)
#define TILE_B2 (128 * 128)     // 16KB
#define STAGE_BG (TILE_A + TILE_B2)   // 48KB

template <bool HALF_OUT>
__global__ __launch_bounds__(256, 1) void gemm_mma(const __half* __restrict__ A,
                                                   const __half* __restrict__ B,
                                                   void* __restrict__ Cv, int N, int K) {
    extern __shared__ __align__(128) char smem[];
    int tid = threadIdx.x;
    int lane = tid & 31, w = tid >> 5;
    int bm = blockIdx.y * 256, bn = blockIdx.x * 128;
    int mw = (w & 3) * 64, nw = (w >> 2) * 64;
    uint32_t sbase = smem_u32(smem);

    float acc[4][8][4];
#pragma unroll
    for (int i = 0; i < 4; i++)
#pragma unroll
        for (int j = 0; j < 8; j++)
#pragma unroll
            for (int q = 0; q < 4; q++) acc[i][j][q] = 0.f;

    const int NC = K / BKG;

    auto issue = [&](int c, int buf) {
        uint32_t st = sbase + buf * STAGE_BG;
        int kc = c * BKG;
        // A: 256 rows x 8 chunks = 2048 units
#pragma unroll
        for (int k = 0; k < 8; k++) {
            int idx = tid + 256 * k;
            int r = idx >> 3, cc = idx & 7;
            cp_async16(st + sw128(r, cc), A + (size_t)(bm + r) * K + kc + cc * 8);
        }
        // B: 128 rows x 8 chunks = 1024 units
#pragma unroll
        for (int k = 0; k < 4; k++) {
            int idx = tid + 256 * k;
            int r = idx >> 3, cc = idx & 7;
            cp_async16(st + TILE_A + sw128(r, cc),
                       B + (size_t)(bn + r) * K + kc + cc * 8);
        }
    };

    issue(0, 0); CP_COMMIT();
    issue(1, 1); CP_COMMIT();

    int rA = mw + (lane & 15);
    int rB = nw + (lane & 15);

    for (int c = 0; c < NC; c++) {
        CP_WAIT(1);
        __syncthreads();

        uint32_t st = sbase + (c % 3) * STAGE_BG;
#pragma unroll
        for (int k16 = 0; k16 < 4; k16++) {
            int cchunk = k16 * 2 + (lane >> 4);
            uint32_t ah[4][4];
#pragma unroll
            for (int mi = 0; mi < 4; mi++)
                ldsm4(ah[mi], st + sw128(rA + mi * 16, cchunk));
#pragma unroll
            for (int ni = 0; ni < 4; ni++) {
                uint32_t b[4];
                ldsm4(b, st + TILE_A + sw128(rB + ni * 16, cchunk));
#pragma unroll
                for (int mi = 0; mi < 4; mi++)
#pragma unroll
                    for (int s = 0; s < 2; s++)
                        mma16816(acc[mi][ni * 2 + s], ah[mi], b[s], b[2 + s]);
            }
        }
        if (c + 2 < NC) issue(c + 2, (c + 2) % 3);
        CP_COMMIT();
    }

    int gid = lane >> 2, q = lane & 3;
#pragma unroll
    for (int mi = 0; mi < 4; mi++)
#pragma unroll
        for (int j = 0; j < 8; j++) {
            int row = bm + mw + mi * 16 + gid;
            int col = bn + nw + j * 8 + q * 2;
            if constexpr (HALF_OUT) {
                __half* C = (__half*)Cv;
                *(uint32_t*)&C[(size_t)row * N + col] =
                    pack2h(acc[mi][j][0], acc[mi][j][1]);
                *(uint32_t*)&C[(size_t)(row + 8) * N + col] =
                    pack2h(acc[mi][j][2], acc[mi][j][3]);
            } else {
                float* C = (float*)Cv;
                *(float2*)&C[(size_t)row * N + col] =
                    make_float2(acc[mi][j][0], acc[mi][j][1]);
                *(float2*)&C[(size_t)(row + 8) * N + col] =
                    make_float2(acc[mi][j][2], acc[mi][j][3]);
            }
        }
}

// ---------------- RoPE: Q (scaled) + K -> fp16, vectorized ----------------
__global__ __launch_bounds__(256) void rope_qk(const float* __restrict__ cosb,
                                               const float* __restrict__ sinb) {
    int idx = blockIdx.x * 256 + threadIdx.x;       // T*20*16 threads
    if (idx >= T_SEQ * 20 * 16) return;
    int d4 = idx & 15;
    int h = (idx >> 4) % 20;
    int t = idx / 320;
    int d = d4 * 4;
    float4 cv = *(const float4*)&cosb[t * 64 + d];
    float4 sv = *(const float4*)&sinb[t * 64 + d];
    float cs[4] = {cv.x, cv.y, cv.z, cv.w};
    float sn[4] = {sv.x, sv.y, sv.z, sv.w};

    int base = (h < 16) ? (t * QKV_DIM + (h >> 2) * 768 + (h & 3) * 128)
                        : (t * QKV_DIM + (h - 16) * 768 + 512);
    uint2 u1 = *(const uint2*)&g_qkvh[base + d];
    uint2 u2 = *(const uint2*)&g_qkvh[base + 64 + d];
    __half2* h1 = (__half2*)&u1;
    __half2* h2 = (__half2*)&u2;
    float x1[4] = {__low2float(h1[0]), __high2float(h1[0]),
                   __low2float(h1[1]), __high2float(h1[1])};
    float x2[4] = {__low2float(h2[0]), __high2float(h2[0]),
                   __low2float(h2[1]), __high2float(h2[1])};
    float o1[4], o2[4];
#pragma unroll
    for (int k = 0; k < 4; k++) {
        o1[k] = x1[k] * cs[k] - x2[k] * sn[k];
        o2[k] = x2[k] * cs[k] + x1[k] * sn[k];
    }
    if (h < 16) {
#pragma unroll
        for (int k = 0; k < 4; k++) { o1[k] *= SCALE_LOG2; o2[k] *= SCALE_LOG2; }
        size_t o = (size_t)t * 2048 + h * 128 + d;
        *(uint2*)&g_qh[o]      = make_uint2(pack2h(o1[0], o1[1]), pack2h(o1[2], o1[3]));
        *(uint2*)&g_qh[o + 64] = make_uint2(pack2h(o2[0], o2[1]), pack2h(o2[2], o2[3]));
    } else {
        size_t o = ((size_t)(h - 16) * T_SEQ + t) * 128 + d;
        *(uint2*)&g_kh[o]      = make_uint2(pack2h(o1[0], o1[1]), pack2h(o1[2], o1[3]));
        *(uint2*)&g_kh[o + 64] = make_uint2(pack2h(o2[0], o2[1]), pack2h(o2[2], o2[3]));
    }
}

// ---------------- mma.sync flash attention (unchanged from R14) ----------------
// 64 q-rows/CTA, 4 warps, Bc=64, 2-stage KV, 2 CTAs/SM.
// P via ex2.approx.f16x2; row-sums l via ones-mma. smem 80KB.
#define AT_Q_BYTES 16384
#define AT_STG_OFF 16384
#define AT_STG_B   32768
#define ONES_H2 0x3C003C00u

__global__ __launch_bounds__(128, 2) void attn_mma() {
    extern __shared__ __align__(128) char smem[];
    uint32_t sb = smem_u32(smem);
    int tid = threadIdx.x;
    int lane = tid & 31, w = tid >> 5;          // 4 warps
    int qb = 63 - blockIdx.x;                   // longest first
    int h = blockIdx.y;
    int g = h >> 2;
    int rw = w * 16;
    int ktmax = qb;

    // ---- Q load (64 rows) ----
#pragma unroll
    for (int i = 0; i < 8; i++) {
        int chunk = tid + 128 * i;              // 0..1023
        int r = chunk >> 4, cd = chunk & 15;
        size_t src = (size_t)(qb * 64 + r) * 2048 + h * 128 + cd * 8;
        cp_async16(sb + (cd >> 2) * 4096 + sw_off(r, cd & 3), g_qh + src);
    }

    auto issueKV = [&](int kt, int stg) {
        uint32_t st = sb + AT_STG_OFF + stg * AT_STG_B;
#pragma unroll
        for (int i = 0; i < 8; i++) {
            int chunk = tid + 128 * i;
            int r = chunk >> 4, cd = chunk & 15;
            size_t src = ((size_t)g * T_SEQ + kt * 64 + r) * 128 + cd * 8;
            cp_async16(st + (cd >> 2) * 4096 + sw_off(r, cd & 3), g_kh + src);
        }
#pragma unroll
        for (int i = 0; i < 8; i++) {
            int chunk = tid + 128 * i;
            int r = chunk >> 4, cd = chunk & 15;
            size_t src = (size_t)(kt * 64 + r) * QKV_DIM + g * 768 + 640 + cd * 8;
            cp_async16(st + 16384 + (cd >> 2) * 4096 + sw_off(r, cd & 3),
                       g_qkvh + src);
        }
    };

    issueKV(0, 0); CP_COMMIT();
    if (1 <= ktmax) issueKV(1, 1);
    CP_COMMIT();

    float oacc[16][4];
#pragma unroll
    for (int i = 0; i < 16; i++)
#pragma unroll
        for (int j = 0; j < 4; j++) oacc[i][j] = 0.f;
    float lacc[4] = {0.f, 0.f, 0.f, 0.f};
    float mi0 = -1e30f, mi1 = -1e30f;

    int rK = lane & 15, cH = lane >> 4;
    int qr1 = qb * 64 + rw + (lane >> 2);

    for (int kt = 0; kt <= ktmax; kt++) {
        CP_WAIT(1);
        __syncthreads();

        uint32_t KH = sb + AT_STG_OFF + (kt & 1) * AT_STG_B;
        uint32_t VH = KH + 16384;

        // ---- S = Q K^T (log2-scaled), batched ldsm ----
        float s[8][4];
#pragma unroll
        for (int j = 0; j < 8; j++)
#pragma unroll
            for (int e = 0; e < 4; e++) s[j][e] = 0.f;

#pragma unroll
        for (int kk = 0; kk < 8; kk++) {
            int c = ((kk & 1) << 1) + cH;
            uint32_t ah[4], kh[4][4];
            ldsm4(ah, sb + (kk >> 1) * 4096 + sw_off(rw + rK, c));
            uint32_t kpan = KH + (kk >> 1) * 4096;
#pragma unroll
            for (int ni = 0; ni < 4; ni++)
                ldsm4(kh[ni], kpan + sw_off(ni * 16 + rK, c));
#pragma unroll
            for (int ni = 0; ni < 4; ni++)
#pragma unroll
                for (int ss = 0; ss < 2; ss++)
                    mma16816(s[ni * 2 + ss], ah, kh[ni][ss], kh[ni][2 + ss]);
        }

        // ---- causal mask (diagonal tile only: kt == qb) ----
        if (kt == qb) {
            int colb = kt * 64 + ((lane & 3) << 1);
#pragma unroll
            for (int j = 0; j < 8; j++) {
                int c0 = colb + j * 8;
                if (c0 > qr1)     s[j][0] = -1e30f;
                if (c0 + 1 > qr1) s[j][1] = -1e30f;
                if (c0 > qr1 + 8)     s[j][2] = -1e30f;
                if (c0 + 1 > qr1 + 8) s[j][3] = -1e30f;
            }
        }

        // ---- online softmax (base-2): max, alpha, P in fp16 ----
        float mx0 = -1e30f, mx1 = -1e30f;
#pragma unroll
        for (int j = 0; j < 8; j++) {
            mx0 = fmaxf(mx0, fmaxf(s[j][0], s[j][1]));
            mx1 = fmaxf(mx1, fmaxf(s[j][2], s[j][3]));
        }
        mx0 = fmaxf(mx0, __shfl_xor_sync(0xffffffffu, mx0, 1));
        mx0 = fmaxf(mx0, __shfl_xor_sync(0xffffffffu, mx0, 2));
        mx1 = fmaxf(mx1, __shfl_xor_sync(0xffffffffu, mx1, 1));
        mx1 = fmaxf(mx1, __shfl_xor_sync(0xffffffffu, mx1, 2));
        float mn0 = fmaxf(mi0, mx0), mn1 = fmaxf(mi1, mx1);
        float a0 = exp2f(mi0 - mn0), a1 = exp2f(mi1 - mn1);
        mi0 = mn0; mi1 = mn1;

        uint32_t ph[8][2];
#pragma unroll
        for (int j = 0; j < 8; j++) {
            ph[j][0] = ex2h2(pack2h(s[j][0] - mn0, s[j][1] - mn0));
            ph[j][1] = ex2h2(pack2h(s[j][2] - mn1, s[j][3] - mn1));
        }

        if (a0 != 1.f || a1 != 1.f) {
#pragma unroll
            for (int ni = 0; ni < 16; ni++) {
                oacc[ni][0] *= a0; oacc[ni][1] *= a0;
                oacc[ni][2] *= a1; oacc[ni][3] *= a1;
            }
            lacc[0] *= a0; lacc[1] *= a0;
            lacc[2] *= a1; lacc[3] *= a1;
        }

        // ---- O += P V (trans-V) and l += P·1 via ones-mma ----
#pragma unroll
        for (int kk2 = 0; kk2 < 4; kk2++) {
            uint32_t hp[4] = {ph[2 * kk2][0], ph[2 * kk2][1],
                              ph[2 * kk2 + 1][0], ph[2 * kk2 + 1][1]};
            mma16816(lacc, hp, ONES_H2, ONES_H2);
            int trow = kk2 * 16 + rK;
#pragma unroll
            for (int g2 = 0; g2 < 2; g2++) {
                uint32_t vh[4][4];
#pragma unroll
                for (int n2 = 0; n2 < 4; n2++) {
                    int nd = g2 * 4 + n2;
                    int cd = nd * 2 + cH;
                    ldsm4t(vh[n2], VH + (cd >> 2) * 4096 + sw_off(trow, cd & 3));
                }
#pragma unroll
                for (int n2 = 0; n2 < 4; n2++) {
                    int nd = g2 * 4 + n2;
                    mma16816(oacc[nd * 2 + 0], hp, vh[n2][0], vh[n2][1]);
                    mma16816(oacc[nd * 2 + 1], hp, vh[n2][2], vh[n2][3]);
                }
            }
        }

        __syncthreads();
        if (kt + 2 <= ktmax) issueKV(kt + 2, (kt + 2) & 1);
        CP_COMMIT();
    }

    // ---- epilogue: O/l -> fp16 ----
    float inv0 = 1.f / lacc[0], inv1 = 1.f / lacc[2];
    size_t row1 = (size_t)qr1 * 2048 + h * 128;
    size_t row2 = row1 + (size_t)8 * 2048;
#pragma unroll
    for (int ni = 0; ni < 16; ni++) {
        int colo = ni * 8 + ((lane & 3) << 1);
        *(uint32_t*)&g_yh[row1 + colo] = pack2h(oacc[ni][0] * inv0, oacc[ni][1] * inv0);
        *(uint32_t*)&g_yh[row2 + colo] = pack2h(oacc[ni][2] * inv1, oacc[ni][3] * inv1);
    }
}

// ---------------- launch ----------------
extern "C" void kernel_launch(void* const* d_in, const int* in_sizes, int n_in,
                              void* d_out, int out_size) {
    const float* x    = (const float*)d_in[0];
    const float* cosb = (const float*)d_in[1];
    const float* sinb = (const float*)d_in[2];
    const float* Wa   = (const float*)d_in[3];
    const float* Wp   = (const float*)d_in[4];
    float* out = (float*)d_out;

    __half *qkvh, *xh, *wa, *wp, *yh;
    cudaGetSymbolAddress((void**)&qkvh, g_qkvh);
    cudaGetSymbolAddress((void**)&xh, g_xh);
    cudaGetSymbolAddress((void**)&wa, g_wa);
    cudaGetSymbolAddress((void**)&wp, g_wp);
    cudaGetSymbolAddress((void**)&yh, g_yh);

    const int gemm_smem = 3 * STAGE_BG;                // 144 KB
    cudaFuncSetAttribute(gemm_mma<true>,
                         cudaFuncAttributeMaxDynamicSharedMemorySize, gemm_smem);
    cudaFuncSetAttribute(gemm_mma<false>,
                         cudaFuncAttributeMaxDynamicSharedMemorySize, gemm_smem);
    const int attn_smem = AT_STG_OFF + 2 * AT_STG_B;   // 80 KB
    cudaFuncSetAttribute(attn_mma, cudaFuncAttributeMaxDynamicSharedMemorySize, attn_smem);

    // 1) convert x and weights to fp16
    {
        int n4 = T_SEQ * C_DIM / 4;
        conv_fp16<<<(n4 + 1023) / 1024, 256>>>((const float4*)x, (uint32_t*)xh, n4);
        int w4 = QKV_DIM * C_DIM / 4;
        conv_fp16<<<(w4 + 1023) / 1024, 256>>>((const float4*)Wa, (uint32_t*)wa, w4);
        int p4 = C_DIM * C_DIM / 4;
        conv_fp16<<<(p4 + 1023) / 1024, 256>>>((const float4*)Wp, (uint32_t*)wp, p4);
    }

    // 2) qkv = x @ W_attn^T  (fp16 output)  — CTA tile 256x128
    gemm_mma<true><<<dim3(QKV_DIM / 128, T_SEQ / 256), 256, gemm_smem>>>(
        xh, wa, qkvh, QKV_DIM, C_DIM);

    // 3) rope (Q + K); V consumed in-place by attention
    rope_qk<<<(T_SEQ * 20 * 16) / 256, 256>>>(cosb, sinb);

    // 4) attention (64-row CTAs, 4 warps, 2 CTAs/SM)
    attn_mma<<<dim3(64, NHEAD), 128, attn_smem>>>();

    // 5) out = y @ W_proj^T  (fp32 output)
    gemm_mma<false><<<dim3(C_DIM / 128, T_SEQ / 256), 256, gemm_smem>>>(
        yh, wp, out, C_DIM, C_DIM);
}

// round 16
// speedup vs baseline: 1.0365x; 1.0365x over previous
#include <cuda_runtime.h>
#include <cuda_fp16.h>
#include <math.h>
#include <stdint.h>

#define T_SEQ 4096
#define C_DIM 2048
#define NHEAD 16
#define HS 128
#define NQG 4
#define QKV_DIM 3072
#define SCALE_LOG2 0.1275071050830161f       // (1/sqrt(128)) * log2(e)

// ---------------- scratch ----------------
__device__ __half g_qkvh[T_SEQ * QKV_DIM];    // qkv as fp16 (GEMM1 output)

__device__ __half g_xh[T_SEQ * C_DIM];        // x as fp16
__device__ __half g_wa[QKV_DIM * C_DIM];
__device__ __half g_wp[C_DIM * C_DIM];

__device__ __half g_qh[T_SEQ * NHEAD * HS];   // [t][h*128+d], scaled by SCALE_LOG2
__device__ __half g_kh[NQG * T_SEQ * HS];     // [g][t][d]
__device__ __half g_yh[T_SEQ * C_DIM];        // attention out, fp16

// ---------------- PTX helpers ----------------
__device__ __forceinline__ uint32_t smem_u32(const void* p) {
    uint32_t a;
    asm("{ .reg .u64 t; cvta.to.shared.u64 t, %1; cvt.u32.u64 %0, t; }"
        : "=r"(a) : "l"(p));
    return a;
}
__device__ __forceinline__ void cp_async16(uint32_t s, const void* g) {
    asm volatile("cp.async.cg.shared.global [%0], [%1], 16;" :: "r"(s), "l"(g));
}
#define CP_COMMIT() asm volatile("cp.async.commit_group;" ::: "memory")
#define CP_WAIT(n)  asm volatile("cp.async.wait_group %0;" :: "n"(n) : "memory")

__device__ __forceinline__ void ldsm4(uint32_t* f, uint32_t a) {
    asm volatile("ldmatrix.sync.aligned.m8n8.x4.shared.b16 {%0,%1,%2,%3}, [%4];"
                 : "=r"(f[0]), "=r"(f[1]), "=r"(f[2]), "=r"(f[3]) : "r"(a));
}
__device__ __forceinline__ void ldsm4t(uint32_t* f, uint32_t a) {
    asm volatile("ldmatrix.sync.aligned.m8n8.x4.trans.shared.b16 {%0,%1,%2,%3}, [%4];"
                 : "=r"(f[0]), "=r"(f[1]), "=r"(f[2]), "=r"(f[3]) : "r"(a));
}
__device__ __forceinline__ void mma16816(float* d, const uint32_t* a,
                                         uint32_t b0, uint32_t b1) {
    asm volatile(
        "mma.sync.aligned.m16n8k16.row.col.f32.f16.f16.f32 "
        "{%0,%1,%2,%3}, {%4,%5,%6,%7}, {%8,%9}, {%0,%1,%2,%3};"
        : "+f"(d[0]), "+f"(d[1]), "+f"(d[2]), "+f"(d[3])
        : "r"(a[0]), "r"(a[1]), "r"(a[2]), "r"(a[3]), "r"(b0), "r"(b1));
}
__device__ __forceinline__ uint32_t pack2h(float lo, float hi) {
    uint32_t r;
    asm("cvt.rn.f16x2.f32 %0, %1, %2;" : "=r"(r) : "f"(hi), "f"(lo));
    return r;
}
__device__ __forceinline__ uint32_t ex2h2(uint32_t x) {
    uint32_t r;
    asm("ex2.approx.f16x2 %0, %1;" : "=r"(r) : "r"(x));
    return r;
}

// 64B-row XOR swizzle (rows of 32 halves, 4x16B chunks) — attention tiles
__device__ __forceinline__ int sw_off(int r, int c) {
    return r * 64 + ((c ^ ((r >> 1) & 3)) << 4);
}
// 128B-row XOR swizzle (rows of 64 halves, 8x16B chunks) — GEMM tiles
__device__ __forceinline__ int sw128(int r, int c) {
    return r * 128 + (((c ^ r) & 7) << 4);
}

// ---------------- fp32 -> fp16 convert, grid-stride x4 ----------------
__global__ __launch_bounds__(256) void conv_fp16(const float4* __restrict__ s,
                                                 uint32_t* __restrict__ h, int n4) {
    int i0 = blockIdx.x * 256 + threadIdx.x;
    int stride = gridDim.x * 256;
#pragma unroll
    for (int k = 0; k < 4; k++) {
        int idx = i0 + k * stride;
        if (idx < n4) {
            float4 v = s[idx];
            h[2 * idx]     = pack2h(v.x, v.y);
            h[2 * idx + 1] = pack2h(v.z, v.w);
        }
    }
}

// ---------------- mma.sync fp16 GEMM: C = A * B^T (R14 config, best known) ----------------
// CTA 128x128, BK=64, 8 warps (4Mx2N), 2 CTAs/SM, 3-stage x 32KB, 1 sync/chunk.
#define BKG 64
#define TILE_BG (128 * 128)     // 16KB per operand tile
#define STAGE_BG (2 * TILE_BG)  // 32KB

template <bool HALF_OUT>
__global__ __launch_bounds__(256, 2) void gemm_mma(const __half* __restrict__ A,
                                                   const __half* __restrict__ B,
                                                   void* __restrict__ Cv, int N, int K) {
    extern __shared__ __align__(128) char smem[];
    int tid = threadIdx.x;
    int lane = tid & 31, w = tid >> 5;
    int bm = blockIdx.y * 128, bn = blockIdx.x * 128;
    int mw = (w & 3) * 32, nw = (w >> 2) * 64;
    uint32_t sbase = smem_u32(smem);

    float acc[2][8][4];
#pragma unroll
    for (int i = 0; i < 2; i++)
#pragma unroll
        for (int j = 0; j < 8; j++)
#pragma unroll
            for (int q = 0; q < 4; q++) acc[i][j][q] = 0.f;

    const int NC = K / BKG;

    auto issue = [&](int c, int buf) {
        uint32_t st = sbase + buf * STAGE_BG;
        int kc = c * BKG;
#pragma unroll
        for (int k = 0; k < 4; k++) {
            int idx = tid + 256 * k;
            int r = idx >> 3, cc = idx & 7;
            int so = sw128(r, cc);
            size_t gA = (size_t)(bm + r) * K + kc + cc * 8;
            size_t gB = (size_t)(bn + r) * K + kc + cc * 8;
            cp_async16(st + so, A + gA);
            cp_async16(st + TILE_BG + so, B + gB);
        }
    };

    issue(0, 0); CP_COMMIT();
    issue(1, 1); CP_COMMIT();

    int rA = mw + (lane & 15);
    int rB = nw + (lane & 15);

    for (int c = 0; c < NC; c++) {
        CP_WAIT(1);
        __syncthreads();

        uint32_t st = sbase + (c % 3) * STAGE_BG;
#pragma unroll
        for (int k16 = 0; k16 < 4; k16++) {
            int cchunk = k16 * 2 + (lane >> 4);
            uint32_t ah[2][4], b[4][4];
            ldsm4(ah[0], st + sw128(rA, cchunk));
            ldsm4(ah[1], st + sw128(rA + 16, cchunk));
#pragma unroll
            for (int ni = 0; ni < 4; ni++)
                ldsm4(b[ni], st + TILE_BG + sw128(rB + ni * 16, cchunk));
#pragma unroll
            for (int ni = 0; ni < 4; ni++)
#pragma unroll
                for (int s = 0; s < 2; s++) {
                    mma16816(acc[0][ni * 2 + s], ah[0], b[ni][s], b[ni][2 + s]);
                    mma16816(acc[1][ni * 2 + s], ah[1], b[ni][s], b[ni][2 + s]);
                }
        }
        if (c + 2 < NC) issue(c + 2, (c + 2) % 3);
        CP_COMMIT();
    }

    int gid = lane >> 2, q = lane & 3;
#pragma unroll
    for (int mi = 0; mi < 2; mi++)
#pragma unroll
        for (int j = 0; j < 8; j++) {
            int row = bm + mw + mi * 16 + gid;
            int col = bn + nw + j * 8 + q * 2;
            if constexpr (HALF_OUT) {
                __half* C = (__half*)Cv;
                *(uint32_t*)&C[(size_t)row * N + col] =
                    pack2h(acc[mi][j][0], acc[mi][j][1]);
                *(uint32_t*)&C[(size_t)(row + 8) * N + col] =
                    pack2h(acc[mi][j][2], acc[mi][j][3]);
            } else {
                float* C = (float*)Cv;
                *(float2*)&C[(size_t)row * N + col] =
                    make_float2(acc[mi][j][0], acc[mi][j][1]);
                *(float2*)&C[(size_t)(row + 8) * N + col] =
                    make_float2(acc[mi][j][2], acc[mi][j][3]);
            }
        }
}

// ---------------- RoPE: Q (scaled) + K -> fp16, vectorized ----------------
__global__ __launch_bounds__(256) void rope_qk(const float* __restrict__ cosb,
                                               const float* __restrict__ sinb) {
    int idx = blockIdx.x * 256 + threadIdx.x;       // T*20*16 threads
    if (idx >= T_SEQ * 20 * 16) return;
    int d4 = idx & 15;
    int h = (idx >> 4) % 20;
    int t = idx / 320;
    int d = d4 * 4;
    float4 cv = *(const float4*)&cosb[t * 64 + d];
    float4 sv = *(const float4*)&sinb[t * 64 + d];
    float cs[4] = {cv.x, cv.y, cv.z, cv.w};
    float sn[4] = {sv.x, sv.y, sv.z, sv.w};

    int base = (h < 16) ? (t * QKV_DIM + (h >> 2) * 768 + (h & 3) * 128)
                        : (t * QKV_DIM + (h - 16) * 768 + 512);
    uint2 u1 = *(const uint2*)&g_qkvh[base + d];
    uint2 u2 = *(const uint2*)&g_qkvh[base + 64 + d];
    __half2* h1 = (__half2*)&u1;
    __half2* h2 = (__half2*)&u2;
    float x1[4] = {__low2float(h1[0]), __high2float(h1[0]),
                   __low2float(h1[1]), __high2float(h1[1])};
    float x2[4] = {__low2float(h2[0]), __high2float(h2[0]),
                   __low2float(h2[1]), __high2float(h2[1])};
    float o1[4], o2[4];
#pragma unroll
    for (int k = 0; k < 4; k++) {
        o1[k] = x1[k] * cs[k] - x2[k] * sn[k];
        o2[k] = x2[k] * cs[k] + x1[k] * sn[k];
    }
    if (h < 16) {
#pragma unroll
        for (int k = 0; k < 4; k++) { o1[k] *= SCALE_LOG2; o2[k] *= SCALE_LOG2; }
        size_t o = (size_t)t * 2048 + h * 128 + d;
        *(uint2*)&g_qh[o]      = make_uint2(pack2h(o1[0], o1[1]), pack2h(o1[2], o1[3]));
        *(uint2*)&g_qh[o + 64] = make_uint2(pack2h(o2[0], o2[1]), pack2h(o2[2], o2[3]));
    } else {
        size_t o = ((size_t)(h - 16) * T_SEQ + t) * 128 + d;
        *(uint2*)&g_kh[o]      = make_uint2(pack2h(o1[0], o1[1]), pack2h(o1[2], o1[3]));
        *(uint2*)&g_kh[o + 64] = make_uint2(pack2h(o2[0], o2[1]), pack2h(o2[2], o2[3]));
    }
}

// ---------------- mma.sync flash attention ----------------
// 64 q-rows/CTA, 4 warps, Bc=64, **3-stage KV, single sync/iter**, 2 CTAs/SM.
// P via ex2.approx.f16x2; row-sums l via ones-mma.
// smem: Q[0:16K) stages{K 16K, V 16K} x3 at 16K. Total 112KB.
#define AT_Q_BYTES 16384
#define AT_STG_OFF 16384
#define AT_STG_B   32768
#define ONES_H2 0x3C003C00u

__global__ __launch_bounds__(128, 2) void attn_mma() {
    extern __shared__ __align__(128) char smem[];
    uint32_t sb = smem_u32(smem);
    int tid = threadIdx.x;
    int lane = tid & 31, w = tid >> 5;          // 4 warps
    int qb = 63 - blockIdx.x;                   // longest first
    int h = blockIdx.y;
    int g = h >> 2;
    int rw = w * 16;
    int ktmax = qb;

    // ---- Q load (64 rows; folded into first commit group) ----
#pragma unroll
    for (int i = 0; i < 8; i++) {
        int chunk = tid + 128 * i;              // 0..1023
        int r = chunk >> 4, cd = chunk & 15;
        size_t src = (size_t)(qb * 64 + r) * 2048 + h * 128 + cd * 8;
        cp_async16(sb + (cd >> 2) * 4096 + sw_off(r, cd & 3), g_qh + src);
    }

    auto issueKV = [&](int kt, int stg) {
        uint32_t st = sb + AT_STG_OFF + stg * AT_STG_B;
#pragma unroll
        for (int i = 0; i < 8; i++) {
            int chunk = tid + 128 * i;
            int r = chunk >> 4, cd = chunk & 15;
            size_t src = ((size_t)g * T_SEQ + kt * 64 + r) * 128 + cd * 8;
            cp_async16(st + (cd >> 2) * 4096 + sw_off(r, cd & 3), g_kh + src);
        }
#pragma unroll
        for (int i = 0; i < 8; i++) {
            int chunk = tid + 128 * i;
            int r = chunk >> 4, cd = chunk & 15;
            size_t src = (size_t)(kt * 64 + r) * QKV_DIM + g * 768 + 640 + cd * 8;
            cp_async16(st + 16384 + (cd >> 2) * 4096 + sw_off(r, cd & 3),
                       g_qkvh + src);
        }
    };

    issueKV(0, 0); CP_COMMIT();
    if (1 <= ktmax) issueKV(1, 1);
    CP_COMMIT();

    float oacc[16][4];
#pragma unroll
    for (int i = 0; i < 16; i++)
#pragma unroll
        for (int j = 0; j < 4; j++) oacc[i][j] = 0.f;
    float lacc[4] = {0.f, 0.f, 0.f, 0.f};
    float mi0 = -1e30f, mi1 = -1e30f;

    int rK = lane & 15, cH = lane >> 4;
    int qr1 = qb * 64 + rw + (lane >> 2);

    for (int kt = 0; kt <= ktmax; kt++) {
        CP_WAIT(1);
        __syncthreads();   // stage kt ready for ALL warps; also proves iter kt-1 reads done

        uint32_t KH = sb + AT_STG_OFF + (kt % 3) * AT_STG_B;
        uint32_t VH = KH + 16384;

        // ---- S = Q K^T (log2-scaled), batched ldsm ----
        float s[8][4];
#pragma unroll
        for (int j = 0; j < 8; j++)
#pragma unroll
            for (int e = 0; e < 4; e++) s[j][e] = 0.f;

#pragma unroll
        for (int kk = 0; kk < 8; kk++) {
            int c = ((kk & 1) << 1) + cH;
            uint32_t ah[4], kh[4][4];
            ldsm4(ah, sb + (kk >> 1) * 4096 + sw_off(rw + rK, c));
            uint32_t kpan = KH + (kk >> 1) * 4096;
#pragma unroll
            for (int ni = 0; ni < 4; ni++)
                ldsm4(kh[ni], kpan + sw_off(ni * 16 + rK, c));
#pragma unroll
            for (int ni = 0; ni < 4; ni++)
#pragma unroll
                for (int ss = 0; ss < 2; ss++)
                    mma16816(s[ni * 2 + ss], ah, kh[ni][ss], kh[ni][2 + ss]);
        }

        // ---- causal mask (diagonal tile only: kt == qb) ----
        if (kt == qb) {
            int colb = kt * 64 + ((lane & 3) << 1);
#pragma unroll
            for (int j = 0; j < 8; j++) {
                int c0 = colb + j * 8;
                if (c0 > qr1)     s[j][0] = -1e30f;
                if (c0 + 1 > qr1) s[j][1] = -1e30f;
                if (c0 > qr1 + 8)     s[j][2] = -1e30f;
                if (c0 + 1 > qr1 + 8) s[j][3] = -1e30f;
            }
        }

        // ---- online softmax (base-2): max, alpha, P in fp16 ----
        float mx0 = -1e30f, mx1 = -1e30f;
#pragma unroll
        for (int j = 0; j < 8; j++) {
            mx0 = fmaxf(mx0, fmaxf(s[j][0], s[j][1]));
            mx1 = fmaxf(mx1, fmaxf(s[j][2], s[j][3]));
        }
        mx0 = fmaxf(mx0, __shfl_xor_sync(0xffffffffu, mx0, 1));
        mx0 = fmaxf(mx0, __shfl_xor_sync(0xffffffffu, mx0, 2));
        mx1 = fmaxf(mx1, __shfl_xor_sync(0xffffffffu, mx1, 1));
        mx1 = fmaxf(mx1, __shfl_xor_sync(0xffffffffu, mx1, 2));
        float mn0 = fmaxf(mi0, mx0), mn1 = fmaxf(mi1, mx1);
        float a0 = exp2f(mi0 - mn0), a1 = exp2f(mi1 - mn1);
        mi0 = mn0; mi1 = mn1;

        uint32_t ph[8][2];
#pragma unroll
        for (int j = 0; j < 8; j++) {
            ph[j][0] = ex2h2(pack2h(s[j][0] - mn0, s[j][1] - mn0));
            ph[j][1] = ex2h2(pack2h(s[j][2] - mn1, s[j][3] - mn1));
        }

        if (a0 != 1.f || a1 != 1.f) {
#pragma unroll
            for (int ni = 0; ni < 16; ni++) {
                oacc[ni][0] *= a0; oacc[ni][1] *= a0;
                oacc[ni][2] *= a1; oacc[ni][3] *= a1;
            }
            lacc[0] *= a0; lacc[1] *= a0;
            lacc[2] *= a1; lacc[3] *= a1;
        }

        // ---- O += P V (trans-V) and l += P·1 via ones-mma ----
#pragma unroll
        for (int kk2 = 0; kk2 < 4; kk2++) {
            uint32_t hp[4] = {ph[2 * kk2][0], ph[2 * kk2][1],
                              ph[2 * kk2 + 1][0], ph[2 * kk2 + 1][1]};
            mma16816(lacc, hp, ONES_H2, ONES_H2);
            int trow = kk2 * 16 + rK;
#pragma unroll
            for (int g2 = 0; g2 < 2; g2++) {
                uint32_t vh[4][4];
#pragma unroll
                for (int n2 = 0; n2 < 4; n2++) {
                    int nd = g2 * 4 + n2;
                    int cd = nd * 2 + cH;
                    ldsm4t(vh[n2], VH + (cd >> 2) * 4096 + sw_off(trow, cd & 3));
                }
#pragma unroll
                for (int n2 = 0; n2 < 4; n2++) {
                    int nd = g2 * 4 + n2;
                    mma16816(oacc[nd * 2 + 0], hp, vh[n2][0], vh[n2][1]);
                    mma16816(oacc[nd * 2 + 1], hp, vh[n2][2], vh[n2][3]);
                }
            }
        }

        // 3-stage: stage (kt+2)%3 was last read at iter kt-1; the sync at top of
        // THIS iteration proved all warps finished iter kt-1 -> safe to overwrite.
        if (kt + 2 <= ktmax) issueKV(kt + 2, (kt + 2) % 3);
        CP_COMMIT();
    }

    // ---- epilogue: O/l -> fp16 ----
    float inv0 = 1.f / lacc[0], inv1 = 1.f / lacc[2];
    size_t row1 = (size_t)qr1 * 2048 + h * 128;
    size_t row2 = row1 + (size_t)8 * 2048;
#pragma unroll
    for (int ni = 0; ni < 16; ni++) {
        int colo = ni * 8 + ((lane & 3) << 1);
        *(uint32_t*)&g_yh[row1 + colo] = pack2h(oacc[ni][0] * inv0, oacc[ni][1] * inv0);
        *(uint32_t*)&g_yh[row2 + colo] = pack2h(oacc[ni][2] * inv1, oacc[ni][3] * inv1);
    }
}

// ---------------- launch ----------------
extern "C" void kernel_launch(void* const* d_in, const int* in_sizes, int n_in,
                              void* d_out, int out_size) {
    const float* x    = (const float*)d_in[0];
    const float* cosb = (const float*)d_in[1];
    const float* sinb = (const float*)d_in[2];
    const float* Wa   = (const float*)d_in[3];
    const float* Wp   = (const float*)d_in[4];
    float* out = (float*)d_out;

    __half *qkvh, *xh, *wa, *wp, *yh;
    cudaGetSymbolAddress((void**)&qkvh, g_qkvh);
    cudaGetSymbolAddress((void**)&xh, g_xh);
    cudaGetSymbolAddress((void**)&wa, g_wa);
    cudaGetSymbolAddress((void**)&wp, g_wp);
    cudaGetSymbolAddress((void**)&yh, g_yh);

    const int gemm_smem = 3 * STAGE_BG;                // 96 KB
    cudaFuncSetAttribute(gemm_mma<true>,
                         cudaFuncAttributeMaxDynamicSharedMemorySize, gemm_smem);
    cudaFuncSetAttribute(gemm_mma<false>,
                         cudaFuncAttributeMaxDynamicSharedMemorySize, gemm_smem);
    const int attn_smem = AT_STG_OFF + 3 * AT_STG_B;   // 112 KB
    cudaFuncSetAttribute(attn_mma, cudaFuncAttributeMaxDynamicSharedMemorySize, attn_smem);

    // 1) convert x and weights to fp16
    {
        int n4 = T_SEQ * C_DIM / 4;
        conv_fp16<<<(n4 + 1023) / 1024, 256>>>((const float4*)x, (uint32_t*)xh, n4);
        int w4 = QKV_DIM * C_DIM / 4;
        conv_fp16<<<(w4 + 1023) / 1024, 256>>>((const float4*)Wa, (uint32_t*)wa, w4);
        int p4 = C_DIM * C_DIM / 4;
        conv_fp16<<<(p4 + 1023) / 1024, 256>>>((const float4*)Wp, (uint32_t*)wp, p4);
    }

    // 2) qkv = x @ W_attn^T  (fp16 output)
    gemm_mma<true><<<dim3(QKV_DIM / 128, T_SEQ / 128), 256, gemm_smem>>>(
        xh, wa, qkvh, QKV_DIM, C_DIM);

    // 3) rope (Q + K); V consumed in-place by attention
    rope_qk<<<(T_SEQ * 20 * 16) / 256, 256>>>(cosb, sinb);

    // 4) attention (64-row CTAs, 4 warps, 2 CTAs/SM, 3-stage KV)
    attn_mma<<<dim3(64, NHEAD), 128, attn_smem>>>();

    // 5) out = y @ W_proj^T  (fp32 output)
    gemm_mma<false><<<dim3(C_DIM / 128, T_SEQ / 128), 256, gemm_smem>>>(
        yh, wp, out, C_DIM, C_DIM);
}